// round 17
// baseline (speedup 1.0000x reference)
#include <cuda_runtime.h>
#include <cuda_fp16.h>

#define H     64
#define NPB   128          // nodes per tile
#define NT    256
#define MAXN  100000
#define SROW  128          // activation row stride (floats)
#define NTILES ((MAXN + NPB - 1) / NPB)
#define PGRID  444         // persistent node grid (3 per SM)

// Scratch (allocation-free rule). g_agg is pre-seeded with x each conv;
// g_xh is an fp16 mirror of x used ONLY for the edge gather (halves that
// L2 stream). Replay-safe: init rewrites all three.
__device__ float   g_x[MAXN * H];
__device__ float   g_agg[MAXN * H];
__device__ __half2 g_xh[MAXN * (H / 2)];
__device__ int     g_ctr[3];         // node work-stealing counters

__device__ __forceinline__ int rotn(int k, int n) {
    return (n + ((k >> 2) << 3) + ((k >> 4) << 2)) & 127;
}

// x = node_emb[z] -> g_x, g_agg, and fp16 mirror g_xh.
__global__ __launch_bounds__(256) void init_kernel(const float* __restrict__ node_emb,
                                                   const int* __restrict__ z,
                                                   int lo, int hi) {
    int t = blockIdx.x * 256 + threadIdx.x;
    int total = (hi - lo) * (H / 4);
    if (t >= total) return;
    int node = lo + (t >> 4);
    int p    = t & 15;
    int zi   = __ldg(z + node);
    float4 v = ((const float4*)node_emb)[zi * 16 + p];
    ((float4*)g_x)[(size_t)node * 16 + p]   = v;
    ((float4*)g_agg)[(size_t)node * 16 + p] = v;
    __half2 h0 = __floats2half2_rn(v.x, v.y);
    __half2 h1 = __floats2half2_rn(v.z, v.w);
    uint2 u; u.x = *(unsigned*)&h0; u.y = *(unsigned*)&h1;
    *(uint2*)(g_xh + (size_t)node * 32 + (p << 1)) = u;
}

// msg = relu(x[src] + edge_attr); vector-RED scatter into g_agg[dst]
// (g_agg pre-seeded with x). x gathered from the fp16 mirror (128B/row).
// 16 threads/edge; adjacent edge pair per thread; loads batched before REDs.
__global__ __launch_bounds__(256) void edge_kernel(const float* __restrict__ ea,
                                                   const int* __restrict__ src,
                                                   const int* __restrict__ dst, int E) {
    int half = E >> 1;
    int t = blockIdx.x * 256 + threadIdx.x;
    if (t >= half * 16) return;
    int grp = t >> 4;                  // handles edges 2*grp, 2*grp+1
    int p   = t & 15;
    int e1  = 2 * grp;

    int2 ss = __ldg((const int2*)src + grp);
    int2 dd = __ldg((const int2*)dst + grp);

    const float4* pe = (const float4*)ea + (size_t)e1 * 16 + p;
    float4 a1 = __ldcs(pe);
    float4 a2 = __ldcs(pe + 16);

    uint2 u1 = *(const uint2*)(g_xh + (size_t)ss.x * 32 + (p << 1));
    uint2 u2 = *(const uint2*)(g_xh + (size_t)ss.y * 32 + (p << 1));
    float2 f1a = __half22float2(*(__half2*)&u1.x);
    float2 f1b = __half22float2(*(__half2*)&u1.y);
    float2 f2a = __half22float2(*(__half2*)&u2.x);
    float2 f2b = __half22float2(*(__half2*)&u2.y);

    float4 m1 = make_float4(fmaxf(a1.x + f1a.x, 0.f), fmaxf(a1.y + f1a.y, 0.f),
                            fmaxf(a1.z + f1b.x, 0.f), fmaxf(a1.w + f1b.y, 0.f));
    float4 m2 = make_float4(fmaxf(a2.x + f2a.x, 0.f), fmaxf(a2.y + f2a.y, 0.f),
                            fmaxf(a2.z + f2b.x, 0.f), fmaxf(a2.w + f2b.y, 0.f));

    float* o1 = g_agg + ((size_t)dd.x << 6) + (p << 2);
    float* o2 = g_agg + ((size_t)dd.y << 6) + (p << 2);
    asm volatile("red.global.add.v4.f32 [%0], {%1, %2, %3, %4};"
                 :: "l"(o1), "f"(m1.x), "f"(m1.y), "f"(m1.z), "f"(m1.w) : "memory");
    asm volatile("red.global.add.v4.f32 [%0], {%1, %2, %3, %4};"
                 :: "l"(o2), "f"(m2.x), "f"(m2.y), "f"(m2.z), "f"(m2.w) : "memory");
}

// Persistent node MLP with dynamic tile stealing (R16 structure).
__global__ __launch_bounds__(NT, 3) void node_kernel(const float* __restrict__ W1g,
                                                     const float* __restrict__ b1g,
                                                     const float* __restrict__ W2g,
                                                     const float* __restrict__ b2g,
                                                     int n, int relu_out,
                                                     float* __restrict__ dout, int last,
                                                     int conv) {
    extern __shared__ float sm[];
    float* sW1 = sm;
    float* sW2 = sm + 4096;
    float* sA  = sm + 8192;
    float* sb1 = sm + 8192 + H * SROW;
    float* sb2 = sb1 + H;
    __shared__ int s_tile;

    int tid = threadIdx.x;

    if (blockIdx.x == 0 && tid == 0) g_ctr[(conv + 1) % 3] = 0;

    for (int idx = tid; idx < H * H; idx += NT) {
        int j = idx >> 6, k = idx & 63;
        sW1[k * H + j] = W1g[idx];
        sW2[k * H + j] = W2g[idx];
    }
    if (tid < H) { sb1[tid] = b1g[tid]; sb2[tid] = b2g[tid]; }

    int jIdx = tid & 15;
    int nIdx = tid >> 4;
    int j0 = jIdx * 4;
    int n0 = nIdx * 8;

    if (tid == 0) s_tile = atomicAdd(&g_ctr[conv], 1);
    __syncthreads();

    float4 b1v = *(const float4*)(sb1 + j0);
    float4 b2v = *(const float4*)(sb2 + j0);
    float* xout = last ? dout : g_x;

    for (;;) {
        int tile = s_tile;
        if (tile >= NTILES) break;
        int base = tile * NPB;

        // ---- Prologue: load g_agg (= x + Σmsg), transpose+rotate into sA.
        #pragma unroll
        for (int it = 0; it < 8; ++it) {
            int idx = tid + it * NT;
            int row = idx >> 4, c = (idx & 15) << 2, g = base + row;
            float4 v = make_float4(0.f, 0.f, 0.f, 0.f);
            if (g < n)
                v = *(const float4*)(g_agg + (size_t)g * H + c);
            float* rowp = sA + c * SROW + rotn(c, row);
            rowp[0]        = v.x;
            rowp[SROW]     = v.y;
            rowp[2 * SROW] = v.z;
            rowp[3 * SROW] = v.w;
        }
        __syncthreads();

        float acc[8][4];

        // ---- Layer 1 ----
        #pragma unroll
        for (int q = 0; q < 8; ++q)
            #pragma unroll
            for (int jj = 0; jj < 4; ++jj) acc[q][jj] = 0.f;

        #pragma unroll 4
        for (int kk = 0; kk < H / 4; ++kk) {
            int kb = kk * 4;
            const float* pA = sA + kb * SROW + rotn(kb, n0);
            const float* pB = sA + kb * SROW + rotn(kb, n0 + 4);
            const float* pW = sW1 + kb * H + j0;
            #pragma unroll
            for (int dk = 0; dk < 4; ++dk) {
                float4 aA = *(const float4*)(pA + dk * SROW);
                float4 aB = *(const float4*)(pB + dk * SROW);
                float4 w  = *(const float4*)(pW + dk * H);
                float av_[8] = {aA.x, aA.y, aA.z, aA.w, aB.x, aB.y, aB.z, aB.w};
                float wv_[4] = {w.x, w.y, w.z, w.w};
                #pragma unroll
                for (int q = 0; q < 8; ++q)
                    #pragma unroll
                    for (int jj = 0; jj < 4; ++jj)
                        acc[q][jj] = fmaf(av_[q], wv_[jj], acc[q][jj]);
            }
        }
        __syncthreads();

        // h1 = relu(acc + b1) -> sA
        #pragma unroll
        for (int jj = 0; jj < 4; ++jj) {
            float b = (jj == 0) ? b1v.x : (jj == 1) ? b1v.y : (jj == 2) ? b1v.z : b1v.w;
            int kr = j0 + jj;
            float* rowp = sA + kr * SROW;
            #pragma unroll
            for (int p = 0; p < 4; ++p) {
                float2 hv = make_float2(fmaxf(acc[2 * p][jj] + b, 0.f),
                                        fmaxf(acc[2 * p + 1][jj] + b, 0.f));
                *(float2*)(rowp + rotn(kr, n0 + 2 * p)) = hv;
            }
        }
        __syncthreads();

        // ---- Layer 2 ----
        #pragma unroll
        for (int q = 0; q < 8; ++q)
            #pragma unroll
            for (int jj = 0; jj < 4; ++jj) acc[q][jj] = 0.f;

        #pragma unroll 4
        for (int kk = 0; kk < H / 4; ++kk) {
            int kb = kk * 4;
            const float* pA = sA + kb * SROW + rotn(kb, n0);
            const float* pB = sA + kb * SROW + rotn(kb, n0 + 4);
            const float* pW = sW2 + kb * H + j0;
            #pragma unroll
            for (int dk = 0; dk < 4; ++dk) {
                float4 aA = *(const float4*)(pA + dk * SROW);
                float4 aB = *(const float4*)(pB + dk * SROW);
                float4 w  = *(const float4*)(pW + dk * H);
                float av_[8] = {aA.x, aA.y, aA.z, aA.w, aB.x, aB.y, aB.z, aB.w};
                float wv_[4] = {w.x, w.y, w.z, w.w};
                #pragma unroll
                for (int q = 0; q < 8; ++q)
                    #pragma unroll
                    for (int jj = 0; jj < 4; ++jj)
                        acc[q][jj] = fmaf(av_[q], wv_[jj], acc[q][jj]);
            }
        }

        if (tid == 0) s_tile = atomicAdd(&g_ctr[conv], 1);

        // ---- Epilogue: +b2, optional relu, +residual; store x (+mirrors) ----
        #pragma unroll
        for (int q = 0; q < 8; ++q) {
            int g = base + n0 + q;
            if (g < n) {
                float4 o = make_float4(acc[q][0] + b2v.x, acc[q][1] + b2v.y,
                                       acc[q][2] + b2v.z, acc[q][3] + b2v.w);
                if (relu_out) {
                    o.x = fmaxf(o.x, 0.f); o.y = fmaxf(o.y, 0.f);
                    o.z = fmaxf(o.z, 0.f); o.w = fmaxf(o.w, 0.f);
                }
                size_t off = (size_t)g * H + j0;
                float4 r = *(const float4*)(g_x + off);
                o.x += r.x; o.y += r.y; o.z += r.z; o.w += r.w;
                *(float4*)(xout + off) = o;
                if (!last) {
                    *(float4*)(g_agg + off) = o;   // seed next conv's aggregation
                    __half2 h0 = __floats2half2_rn(o.x, o.y);
                    __half2 h1 = __floats2half2_rn(o.z, o.w);
                    uint2 u; u.x = *(unsigned*)&h0; u.y = *(unsigned*)&h1;
                    *(uint2*)(g_xh + (size_t)g * 32 + (j0 >> 1)) = u;
                }
            }
        }
        __syncthreads();
    }
}

static const int NODE_SMEM_BYTES = (8192 + H * SROW + 2 * H) * (int)sizeof(float);

extern "C" void kernel_launch(void* const* d_in, const int* in_sizes, int n_in,
                              void* d_out, int out_size) {
    const float* node_emb  = (const float*)d_in[0];
    const float* W1        = (const float*)d_in[1];
    const float* b1        = (const float*)d_in[2];
    const float* W2        = (const float*)d_in[3];
    const float* b2        = (const float*)d_in[4];
    const float* edge_attr = (const float*)d_in[5];
    const int*   z         = (const int*)d_in[6];
    const int*   eidx      = (const int*)d_in[7];

    int n = in_sizes[6];        // 100000 nodes
    int E = in_sizes[7] / 2;    // 1000000 edges
    float* out = (float*)d_out;

    cudaFuncSetAttribute(node_kernel, cudaFuncAttributeMaxDynamicSharedMemorySize,
                         NODE_SMEM_BYTES);

    int nh = n / 2;
    init_kernel<<<(nh * (H / 4) + 255) / 256, 256>>>(node_emb, z, 0, nh);
    init_kernel<<<((n - nh) * (H / 4) + 255) / 256, 256>>>(node_emb, z, nh, n);

    int edge_blocks = ((E / 2) * 16 + 255) / 256;

    for (int i = 0; i < 3; ++i) {
        edge_kernel<<<edge_blocks, 256>>>(edge_attr, eidx, eidx + E, E);
        node_kernel<<<PGRID, NT, NODE_SMEM_BYTES>>>(
            W1 + i * H * H, b1 + i * H, W2 + i * H * H, b2 + i * H,
            n, /*relu_out=*/(i < 2) ? 1 : 0, out, /*last=*/(i == 2) ? 1 : 0, i);
    }
}